// round 3
// baseline (speedup 1.0000x reference)
#include <cuda_runtime.h>
#include <math.h>

#define NN 50000
#define EE 800000
#define HID 64
#define NH 3
#define D1 192   // NH*HID

// ---------------- scratch (device globals; no allocation allowed) ----------------
__device__ float g_h[NN*HID];        // encoder output
__device__ float g_xs1[NN*D1];       // h @ W1_src
__device__ float g_as1[NN*4];        // per-node a_src (3 used, padded)
__device__ float g_ad1[NN*4];        // per-node a_dst
__device__ int   g_src[EE];
__device__ int   g_dst[EE];
__device__ int   g_deg[NN];
__device__ int   g_rowptr[NN+1];
__device__ int   g_cursor[NN];
__device__ int   g_eid[EE];          // edge ids grouped by dst (CSR)
__device__ float g_h1[NN*D1];        // layer-1 output after bias+elu
__device__ float g_xs2[NN];          // h1 @ W2_src
__device__ float g_a2s[NN];          // xs2 * att2_src
__device__ float g_a2d[NN];          // (h1 @ W2_dst) * att2_dst
__device__ float g_wdatt[HID*NH];    // folded W1_dst*att1_dst  [k*3+h]
__device__ float g_ce1[NH];
__device__ int   g_is64;

// ---------------- dtype detection for edge_index (int64 vs int32) ----------------
__global__ void k_detect(const int* ei){
    if (threadIdx.x == 0){
        int all0 = 1;
        for (int i = 0; i < 64; i++) if (ei[2*i+1] != 0) all0 = 0;
        g_is64 = all0;   // int64 little-endian: high words of small values are 0
    }
}

// ---------------- fold attention vectors into weights ----------------
__global__ void k_pre(const float* W1_dst, const float* att1_dst,
                      const float* W1_edge, const float* att1_edge){
    int tid = threadIdx.x;
    if (tid < 192){
        int k = tid / 3, h = tid % 3;
        float s = 0.f;
        #pragma unroll 8
        for (int c = 0; c < HID; c++)
            s += W1_dst[k*D1 + h*HID + c] * att1_dst[h*HID + c];
        g_wdatt[k*3 + h] = s;
    }
    if (tid < 3){
        float s = 0.f;
        #pragma unroll 8
        for (int c = 0; c < HID; c++)
            s += W1_edge[tid*HID + c] * att1_edge[tid*HID + c];
        g_ce1[tid] = s;
    }
}

// ---------------- node encoder ----------------
__global__ void k_enc(const float* __restrict__ x,
                      const float* __restrict__ Wc, const float* __restrict__ bc,
                      const float* __restrict__ Wt, const float* __restrict__ bt){
    int idx = blockIdx.x * blockDim.x + threadIdx.x;
    if (idx >= NN*HID) return;
    int n = idx >> 6, j = idx & 63;
    float mask = x[n*5 + 0];
    float f0 = x[n*5+1], f1 = x[n*5+2], f2 = x[n*5+3];
    float comm = f0*Wc[j] + f1*Wc[HID + j] + bc[j];
    float toll = f2*Wt[j] + bt[j];
    float v = comm*(1.f - mask) + toll*mask;
    g_h[idx] = v > 0.f ? v : expm1f(v);
}

// ---------------- xs1 = h@W1_src, plus per-node a_src / a_dst ----------------
__global__ void __launch_bounds__(192) k_xs(const float* __restrict__ W1_src,
                                            const float* __restrict__ att1_src){
    __shared__ float sh[HID];
    __shared__ float wsum[6];
    int n = blockIdx.x, tid = threadIdx.x;
    int lane = tid & 31, wp = tid >> 5;
    if (tid < HID) sh[tid] = g_h[n*HID + tid];
    __syncthreads();
    float s = 0.f;
    #pragma unroll
    for (int k = 0; k < HID; k++) s += sh[k] * __ldg(&W1_src[k*D1 + tid]);
    g_xs1[n*D1 + tid] = s;
    // a_src: reduce s*att1_src over each head's 64 channels (2 warps per head)
    float v = s * __ldg(&att1_src[tid]);
    #pragma unroll
    for (int o = 16; o > 0; o >>= 1) v += __shfl_down_sync(0xffffffffu, v, o);
    if (lane == 0) wsum[wp] = v;
    __syncthreads();
    if (tid < 3){
        g_as1[n*4 + tid] = wsum[2*tid] + wsum[2*tid + 1];
        float s2 = 0.f;
        #pragma unroll
        for (int k = 0; k < HID; k++) s2 += sh[k] * g_wdatt[k*3 + tid];
        g_ad1[n*4 + tid] = s2;
    }
}

// ---------------- CSR build ----------------
__global__ void k_zero(){
    int i = blockIdx.x * blockDim.x + threadIdx.x;
    if (i < NN) g_deg[i] = 0;
}

__global__ void k_edges(const void* eiv){
    int e = blockIdx.x * blockDim.x + threadIdx.x;
    if (e >= EE) return;
    int s, d;
    if (g_is64){
        const long long* p = (const long long*)eiv;
        s = (int)p[e]; d = (int)p[EE + e];
    } else {
        const int* p = (const int*)eiv;
        s = p[e]; d = p[EE + e];
    }
    g_src[e] = s; g_dst[e] = d;
    atomicAdd(&g_deg[d], 1);
}

__global__ void k_scan(){
    __shared__ int sh[1024];
    int tid = threadIdx.x;
    const int ITEMS = 49;     // 1024*49 >= NN
    int base = tid * ITEMS;
    int sum = 0;
    for (int i = 0; i < ITEMS; i++){ int idx = base + i; if (idx < NN) sum += g_deg[idx]; }
    sh[tid] = sum; __syncthreads();
    for (int off = 1; off < 1024; off <<= 1){
        int t = (tid >= off) ? sh[tid - off] : 0;
        __syncthreads();
        sh[tid] += t;
        __syncthreads();
    }
    int run = sh[tid] - sum;  // exclusive prefix
    for (int i = 0; i < ITEMS; i++){
        int idx = base + i;
        if (idx < NN){ g_rowptr[idx] = run; g_cursor[idx] = run; run += g_deg[idx]; }
    }
    if (tid == 1023) g_rowptr[NN] = sh[1023];
}

__global__ void k_scatter(){
    int e = blockIdx.x * blockDim.x + threadIdx.x;
    if (e >= EE) return;
    int d = g_dst[e];
    int p = atomicAdd(&g_cursor[d], 1);
    g_eid[p] = e;
}

// ---------------- layer-1 pull aggregation + fused layer-2 projections ----------------
__device__ __forceinline__ float lrelu(float v){ return v > 0.f ? v : 0.2f*v; }

__global__ void __launch_bounds__(192) k_l1(const float* __restrict__ edge_attr,
                                            const float* __restrict__ b1,
                                            const float* __restrict__ W2_src,
                                            const float* __restrict__ W2_dst,
                                            const float* __restrict__ att2_src,
                                            const float* __restrict__ att2_dst){
    __shared__ float s_w[32*4];
    __shared__ int   s_sid[32];
    __shared__ float s_wred[18];
    __shared__ float s_max[3];
    __shared__ float s_den[3];
    __shared__ float s_adst[3];
    __shared__ float s_red[12];

    int n = blockIdx.x;
    int tid = threadIdx.x;
    int lane = tid & 31, wp = tid >> 5;
    int start = g_rowptr[n], deg = g_rowptr[n+1] - start;
    float c0 = g_ce1[0], c1 = g_ce1[1], c2 = g_ce1[2];
    if (tid < 3) s_adst[tid] = g_ad1[n*4 + tid];
    __syncthreads();
    float ad0 = s_adst[0], ad1 = s_adst[1], ad2 = s_adst[2];

    // phase 1: per-head max of leaky(alpha_raw)
    float m0 = -1e30f, m1 = -1e30f, m2 = -1e30f;
    for (int i = tid; i < deg; i += 192){
        int e = __ldg(&g_eid[start + i]);
        int s = __ldg(&g_src[e]);
        float ea = __ldg(&edge_attr[e]);
        float r0 = lrelu(__ldg(&g_as1[s*4+0]) + ad0 + ea*c0);
        float r1 = lrelu(__ldg(&g_as1[s*4+1]) + ad1 + ea*c1);
        float r2 = lrelu(__ldg(&g_as1[s*4+2]) + ad2 + ea*c2);
        m0 = fmaxf(m0, r0); m1 = fmaxf(m1, r1); m2 = fmaxf(m2, r2);
    }
    #pragma unroll
    for (int o = 16; o > 0; o >>= 1){
        m0 = fmaxf(m0, __shfl_down_sync(0xffffffffu, m0, o));
        m1 = fmaxf(m1, __shfl_down_sync(0xffffffffu, m1, o));
        m2 = fmaxf(m2, __shfl_down_sync(0xffffffffu, m2, o));
    }
    if (lane == 0){ s_wred[wp*3+0] = m0; s_wred[wp*3+1] = m1; s_wred[wp*3+2] = m2; }
    __syncthreads();
    if (tid < 3){
        float m = s_wred[tid];
        #pragma unroll
        for (int w = 1; w < 6; w++) m = fmaxf(m, s_wred[w*3 + tid]);
        s_max[tid] = m;
        s_den[tid] = 0.f;
    }
    __syncthreads();
    float mx0 = s_max[0], mx1 = s_max[1], mx2 = s_max[2];

    // phase 2: chunked exp + weighted accumulation (normalization deferred)
    int hh = tid >> 6;             // head of this channel
    float acc = 0.f;
    for (int base = 0; base < deg; base += 32){
        int cn = min(32, deg - base);
        if (tid < cn){
            int e = __ldg(&g_eid[start + base + tid]);
            int s = __ldg(&g_src[e]);
            float ea = __ldg(&edge_attr[e]);
            float r0 = lrelu(__ldg(&g_as1[s*4+0]) + ad0 + ea*c0);
            float r1 = lrelu(__ldg(&g_as1[s*4+1]) + ad1 + ea*c1);
            float r2 = lrelu(__ldg(&g_as1[s*4+2]) + ad2 + ea*c2);
            float w0 = __expf(r0 - mx0);
            float w1 = __expf(r1 - mx1);
            float w2 = __expf(r2 - mx2);
            s_w[tid*4+0] = w0; s_w[tid*4+1] = w1; s_w[tid*4+2] = w2;
            s_sid[tid] = s;
            atomicAdd(&s_den[0], w0);
            atomicAdd(&s_den[1], w1);
            atomicAdd(&s_den[2], w2);
        }
        __syncthreads();
        int i = 0;
        for (; i + 2 <= cn; i += 2){
            float xa = __ldg(&g_xs1[s_sid[i]*D1 + tid]);
            float xb = __ldg(&g_xs1[s_sid[i+1]*D1 + tid]);
            acc += xa * s_w[i*4 + hh] + xb * s_w[(i+1)*4 + hh];
        }
        if (i < cn)
            acc += __ldg(&g_xs1[s_sid[i]*D1 + tid]) * s_w[i*4 + hh];
        __syncthreads();
    }

    float den = s_den[hh];
    float out = acc / (den + 1e-16f) + __ldg(&b1[tid]);
    float hv = out > 0.f ? out : expm1f(out);
    g_h1[n*D1 + tid] = hv;

    // fused layer-2 projections: xs2 = h1.W2_src, xd2 = h1.W2_dst (192->1)
    float vs = hv * __ldg(&W2_src[tid]);
    float vd = hv * __ldg(&W2_dst[tid]);
    #pragma unroll
    for (int o = 16; o > 0; o >>= 1){
        vs += __shfl_down_sync(0xffffffffu, vs, o);
        vd += __shfl_down_sync(0xffffffffu, vd, o);
    }
    if (lane == 0){ s_red[wp] = vs; s_red[6 + wp] = vd; }
    __syncthreads();
    if (tid == 0){
        float xs2 = 0.f, xd2 = 0.f;
        #pragma unroll
        for (int w = 0; w < 6; w++){ xs2 += s_red[w]; xd2 += s_red[6 + w]; }
        g_xs2[n] = xs2;
        g_a2s[n] = xs2 * att2_src[0];
        g_a2d[n] = xd2 * att2_dst[0];
    }
}

// ---------------- layer-2 aggregation (scalar) + final mask ----------------
__global__ void k_l2(const float* __restrict__ edge_attr,
                     const float* __restrict__ x,
                     const float* __restrict__ W2_edge,
                     const float* __restrict__ att2_edge,
                     const float* __restrict__ b2,
                     float* __restrict__ out){
    int gwid = (blockIdx.x * blockDim.x + threadIdx.x) >> 5;
    int lane = threadIdx.x & 31;
    if (gwid >= NN) return;
    int n = gwid;
    int start = g_rowptr[n], deg = g_rowptr[n+1] - start;
    float ce = W2_edge[0] * att2_edge[0];
    float ad = g_a2d[n];

    float m = -1e30f;
    for (int i = lane; i < deg; i += 32){
        int e = __ldg(&g_eid[start + i]);
        float r = lrelu(__ldg(&g_a2s[g_src[e]]) + ad + __ldg(&edge_attr[e])*ce);
        m = fmaxf(m, r);
    }
    #pragma unroll
    for (int o = 16; o > 0; o >>= 1) m = fmaxf(m, __shfl_xor_sync(0xffffffffu, m, o));

    float num = 0.f, den = 0.f;
    for (int i = lane; i < deg; i += 32){
        int e = __ldg(&g_eid[start + i]);
        int s = __ldg(&g_src[e]);
        float r = lrelu(__ldg(&g_a2s[s]) + ad + __ldg(&edge_attr[e])*ce);
        float w = __expf(r - m);
        num += __ldg(&g_xs2[s]) * w;
        den += w;
    }
    #pragma unroll
    for (int o = 16; o > 0; o >>= 1){
        num += __shfl_xor_sync(0xffffffffu, num, o);
        den += __shfl_xor_sync(0xffffffffu, den, o);
    }
    if (lane == 0){
        float v = num / (den + 1e-16f) + b2[0];
        out[n] = v * x[n*5 + 0];
    }
}

// ---------------- launch ----------------
extern "C" void kernel_launch(void* const* d_in, const int* in_sizes, int n_in,
                              void* d_out, int out_size){
    const float* x        = (const float*)d_in[0];
    const void*  ei       = d_in[1];
    const float* eattr    = (const float*)d_in[2];
    const float* W_comm   = (const float*)d_in[3];
    const float* b_comm   = (const float*)d_in[4];
    const float* W_toll   = (const float*)d_in[5];
    const float* b_toll   = (const float*)d_in[6];
    const float* W1_src   = (const float*)d_in[7];
    const float* W1_dst   = (const float*)d_in[8];
    const float* att1_src = (const float*)d_in[9];
    const float* att1_dst = (const float*)d_in[10];
    const float* W1_edge  = (const float*)d_in[11];
    const float* att1_edge= (const float*)d_in[12];
    const float* b1       = (const float*)d_in[13];
    const float* W2_src   = (const float*)d_in[14];
    const float* W2_dst   = (const float*)d_in[15];
    const float* att2_src = (const float*)d_in[16];
    const float* att2_dst = (const float*)d_in[17];
    const float* W2_edge  = (const float*)d_in[18];
    const float* att2_edge= (const float*)d_in[19];
    const float* b2       = (const float*)d_in[20];
    float* out = (float*)d_out;

    k_detect<<<1, 32>>>((const int*)ei);
    k_pre<<<1, 192>>>(W1_dst, att1_dst, W1_edge, att1_edge);
    k_enc<<<(NN*HID + 255)/256, 256>>>(x, W_comm, b_comm, W_toll, b_toll);
    k_zero<<<(NN + 255)/256, 256>>>();
    k_edges<<<(EE + 255)/256, 256>>>(ei);
    k_scan<<<1, 1024>>>();
    k_scatter<<<(EE + 255)/256, 256>>>();
    k_xs<<<NN, 192>>>(W1_src, att1_src);
    k_l1<<<NN, 192>>>(eattr, b1, W2_src, W2_dst, att2_src, att2_dst);
    k_l2<<<(NN + 3)/4, 128>>>(eattr, x, W2_edge, att2_edge, b2, out);
}

// round 5
// speedup vs baseline: 1.5146x; 1.5146x over previous
#include <cuda_runtime.h>
#include <math.h>

#define NN 50000
#define EE 800000
#define HID 64
#define NH 3
#define D1 192   // NH*HID

// ---------------- scratch (device globals) ----------------
__device__ float  g_h[NN*HID];     // encoder output
__device__ float  g_xs1[NN*D1];    // h @ W1_src
__device__ float  g_as1[NN*4];     // per-node a_src (3 used, padded to float4)
__device__ float  g_ad1[NN*4];     // per-node a_dst
__device__ int    g_src[EE];
__device__ int    g_dst[EE];
__device__ int    g_deg[NN];
__device__ int    g_rowptr[NN+1];
__device__ int    g_cursor[NN];
__device__ float4 g_er[EE];        // per-edge {r0,r1,r2,src_bits} grouped by dst
__device__ float  g_eea[EE];       // per-edge edge_attr grouped by dst
__device__ float  g_xs2[NN];       // h1 @ W2_src
__device__ float  g_a2s[NN];       // xs2 * att2_src
__device__ float  g_a2d[NN];       // (h1 @ W2_dst) * att2_dst
__device__ float  g_wdatt[HID*NH]; // folded W1_dst*att1_dst  [k*3+h]
__device__ float  g_ce1[NH];
__device__ int    g_is64;

__device__ __forceinline__ float lrelu(float v){ return v > 0.f ? v : 0.2f*v; }

// ---------------- front: detect + fold + encoder + zero deg ----------------
__global__ void k_front(const float* __restrict__ x,
                        const float* __restrict__ Wc, const float* __restrict__ bc,
                        const float* __restrict__ Wt, const float* __restrict__ bt,
                        const float* __restrict__ W1_dst, const float* __restrict__ att1_dst,
                        const float* __restrict__ W1_edge, const float* __restrict__ att1_edge,
                        const int*   __restrict__ ei){
    int tid = threadIdx.x;
    if (blockIdx.x == (NN*HID)/256){
        // attention folds + dtype detect
        if (tid < 192){
            int k = tid / 3, h = tid % 3;
            float s = 0.f;
            #pragma unroll 8
            for (int c = 0; c < HID; c++)
                s += W1_dst[k*D1 + h*HID + c] * att1_dst[h*HID + c];
            g_wdatt[k*3 + h] = s;
        }
        if (tid >= 192 && tid < 195){
            int hh = tid - 192;
            float s = 0.f;
            #pragma unroll 8
            for (int c = 0; c < HID; c++)
                s += W1_edge[hh*HID + c] * att1_edge[hh*HID + c];
            g_ce1[hh] = s;
        }
        if (tid == 255){
            int all0 = 1;
            for (int i = 0; i < 64; i++) if (ei[2*i+1] != 0) all0 = 0;
            g_is64 = all0;
        }
        return;
    }
    int idx = blockIdx.x * 256 + tid;
    if (idx < NN) g_deg[idx] = 0;
    // encoder
    int n = idx >> 6, j = idx & 63;
    float mask = x[n*5 + 0];
    float f0 = x[n*5+1], f1 = x[n*5+2], f2 = x[n*5+3];
    float comm = f0*Wc[j] + f1*Wc[HID + j] + bc[j];
    float toll = f2*Wt[j] + bt[j];
    float v = comm*(1.f - mask) + toll*mask;
    g_h[idx] = v > 0.f ? v : expm1f(v);
}

// ---------------- edges: decode + degree histogram ----------------
__global__ void k_edges(const void* eiv){
    int e = blockIdx.x * blockDim.x + threadIdx.x;
    if (e >= EE) return;
    int s, d;
    if (g_is64){
        const long long* p = (const long long*)eiv;
        s = (int)p[e]; d = (int)p[EE + e];
    } else {
        const int* p = (const int*)eiv;
        s = p[e]; d = p[EE + e];
    }
    g_src[e] = s; g_dst[e] = d;
    atomicAdd(&g_deg[d], 1);
}

// ---------------- single-block scan ----------------
__global__ void k_scan(){
    __shared__ int sh[1024];
    int tid = threadIdx.x;
    const int ITEMS = 49;     // 1024*49 >= NN
    int base = tid * ITEMS;
    int sum = 0;
    for (int i = 0; i < ITEMS; i++){ int idx = base + i; if (idx < NN) sum += g_deg[idx]; }
    sh[tid] = sum; __syncthreads();
    for (int off = 1; off < 1024; off <<= 1){
        int t = (tid >= off) ? sh[tid - off] : 0;
        __syncthreads();
        sh[tid] += t;
        __syncthreads();
    }
    int run = sh[tid] - sum;  // exclusive prefix
    for (int i = 0; i < ITEMS; i++){
        int idx = base + i;
        if (idx < NN){ g_rowptr[idx] = run; g_cursor[idx] = run; run += g_deg[idx]; }
    }
    if (tid == 1023) g_rowptr[NN] = sh[1023];
}

// ---------------- xs1 = h@W1_src, per-node a_src / a_dst ----------------
__global__ void __launch_bounds__(192) k_xs(const float* __restrict__ W1_src,
                                            const float* __restrict__ att1_src){
    __shared__ float sh[HID];
    __shared__ float wsum[6];
    int n = blockIdx.x, tid = threadIdx.x;
    int lane = tid & 31, wp = tid >> 5;
    if (tid < HID) sh[tid] = g_h[n*HID + tid];
    __syncthreads();
    float s = 0.f;
    #pragma unroll
    for (int k = 0; k < HID; k++) s += sh[k] * __ldg(&W1_src[k*D1 + tid]);
    g_xs1[n*D1 + tid] = s;
    float v = s * __ldg(&att1_src[tid]);
    #pragma unroll
    for (int o = 16; o > 0; o >>= 1) v += __shfl_down_sync(0xffffffffu, v, o);
    if (lane == 0) wsum[wp] = v;
    __syncthreads();
    if (tid < 3){
        g_as1[n*4 + tid] = wsum[2*tid] + wsum[2*tid + 1];
        float s2 = 0.f;
        #pragma unroll
        for (int k = 0; k < HID; k++) s2 += sh[k] * g_wdatt[k*3 + tid];
        g_ad1[n*4 + tid] = s2;
    }
    if (tid == 190) g_as1[n*4 + 3] = 0.f;
    if (tid == 191) g_ad1[n*4 + 3] = 0.f;
}

// ---------------- scatter: CSR + fused per-edge attention logits ----------------
__global__ void k_scatter(const float* __restrict__ edge_attr){
    int e = blockIdx.x * blockDim.x + threadIdx.x;
    if (e >= EE) return;
    int s = g_src[e], d = g_dst[e];
    float ea = __ldg(&edge_attr[e]);
    float4 as = *(const float4*)&g_as1[s*4];
    float4 ad = *(const float4*)&g_ad1[d*4];
    float r0 = lrelu(as.x + ad.x + ea*g_ce1[0]);
    float r1 = lrelu(as.y + ad.y + ea*g_ce1[1]);
    float r2 = lrelu(as.z + ad.z + ea*g_ce1[2]);
    int p = atomicAdd(&g_cursor[d], 1);
    g_er[p] = make_float4(r0, r1, r2, __int_as_float(s));
    g_eea[p] = ea;
}

// ---------------- layer-1 warp-per-node aggregation + fused layer-2 proj ----------------
__global__ void __launch_bounds__(256) k_l1(const float* __restrict__ b1,
                                            const float* __restrict__ W2_src,
                                            const float* __restrict__ W2_dst,
                                            const float* __restrict__ att2_src,
                                            const float* __restrict__ att2_dst){
    __shared__ float4 s_w[8][32];
    int wslot = threadIdx.x >> 5, lane = threadIdx.x & 31;
    int n = blockIdx.x * 8 + wslot;
    if (n >= NN) return;                 // warp-uniform
    int start = g_rowptr[n], deg = g_rowptr[n+1] - start;

    // pass A: per-head max (contiguous reads)
    float m0 = -1e30f, m1 = -1e30f, m2 = -1e30f;
    {
        int i = lane;
        for (; i + 32 < deg; i += 64){
            float4 ea = __ldg(&g_er[start + i]);
            float4 eb = __ldg(&g_er[start + i + 32]);
            m0 = fmaxf(m0, fmaxf(ea.x, eb.x));
            m1 = fmaxf(m1, fmaxf(ea.y, eb.y));
            m2 = fmaxf(m2, fmaxf(ea.z, eb.z));
        }
        if (i < deg){
            float4 ea = __ldg(&g_er[start + i]);
            m0 = fmaxf(m0, ea.x); m1 = fmaxf(m1, ea.y); m2 = fmaxf(m2, ea.z);
        }
    }
    #pragma unroll
    for (int o = 16; o > 0; o >>= 1){
        m0 = fmaxf(m0, __shfl_xor_sync(0xffffffffu, m0, o));
        m1 = fmaxf(m1, __shfl_xor_sync(0xffffffffu, m1, o));
        m2 = fmaxf(m2, __shfl_xor_sync(0xffffffffu, m2, o));
    }

    // pass B: exp weights + gather
    float acc0=0.f,acc1=0.f,acc2=0.f,acc3=0.f,acc4=0.f,acc5=0.f;
    float den0=0.f,den1=0.f,den2=0.f;
    for (int base = 0; base < deg; base += 32){
        int cn = min(32, deg - base);
        if (lane < cn){
            float4 er = __ldg(&g_er[start + base + lane]);
            float w0 = __expf(er.x - m0);
            float w1 = __expf(er.y - m1);
            float w2 = __expf(er.z - m2);
            den0 += w0; den1 += w1; den2 += w2;
            s_w[wslot][lane] = make_float4(w0, w1, w2, er.w);
        }
        __syncwarp();
        #pragma unroll 2
        for (int i = 0; i < cn; i++){
            float4 w = s_w[wslot][i];
            const float* row = &g_xs1[__float_as_int(w.w) * D1];
            acc0 += __ldg(&row[lane      ]) * w.x;
            acc1 += __ldg(&row[lane + 32 ]) * w.x;
            acc2 += __ldg(&row[lane + 64 ]) * w.y;
            acc3 += __ldg(&row[lane + 96 ]) * w.y;
            acc4 += __ldg(&row[lane + 128]) * w.z;
            acc5 += __ldg(&row[lane + 160]) * w.z;
        }
        __syncwarp();
    }
    #pragma unroll
    for (int o = 16; o > 0; o >>= 1){
        den0 += __shfl_xor_sync(0xffffffffu, den0, o);
        den1 += __shfl_xor_sync(0xffffffffu, den1, o);
        den2 += __shfl_xor_sync(0xffffffffu, den2, o);
    }
    float id0 = 1.f/(den0 + 1e-16f), id1 = 1.f/(den1 + 1e-16f), id2 = 1.f/(den2 + 1e-16f);

    // h1 channels for this lane: lane+32c; fused layer-2 projections
    float vs = 0.f, vd = 0.f;
    float accs[6] = {acc0*id0, acc1*id0, acc2*id1, acc3*id1, acc4*id2, acc5*id2};
    #pragma unroll
    for (int c = 0; c < 6; c++){
        int ch = lane + 32*c;
        float o = accs[c] + __ldg(&b1[ch]);
        float hv = o > 0.f ? o : expm1f(o);
        vs += hv * __ldg(&W2_src[ch]);
        vd += hv * __ldg(&W2_dst[ch]);
    }
    #pragma unroll
    for (int o = 16; o > 0; o >>= 1){
        vs += __shfl_xor_sync(0xffffffffu, vs, o);
        vd += __shfl_xor_sync(0xffffffffu, vd, o);
    }
    if (lane == 0){
        g_xs2[n] = vs;
        g_a2s[n] = vs * att2_src[0];
        g_a2d[n] = vd * att2_dst[0];
    }
}

// ---------------- layer-2 warp-per-node aggregation + final mask ----------------
__global__ void __launch_bounds__(256) k_l2(const float* __restrict__ x,
                                            const float* __restrict__ W2_edge,
                                            const float* __restrict__ att2_edge,
                                            const float* __restrict__ b2,
                                            float* __restrict__ out){
    int wslot = threadIdx.x >> 5, lane = threadIdx.x & 31;
    int n = blockIdx.x * 8 + wslot;
    if (n >= NN) return;
    int start = g_rowptr[n], deg = g_rowptr[n+1] - start;
    float ce = W2_edge[0] * att2_edge[0];
    float ad = g_a2d[n];

    // pass 1: max, with 2-slot register cache (covers deg <= 64)
    float rA = -1e30f, rB = -1e30f;
    int   sA = -1,     sB = -1;
    float m = -1e30f;
    int nIter = (deg + 31) >> 5;
    for (int j = 0; j < nIter; j++){
        int i = lane + 32*j;
        if (i < deg){
            float4 er = __ldg(&g_er[start + i]);
            int s = __float_as_int(er.w);
            float ea = __ldg(&g_eea[start + i]);
            float r = lrelu(__ldg(&g_a2s[s]) + ad + ea*ce);
            if (j == 0){ rA = r; sA = s; }
            else if (j == 1){ rB = r; sB = s; }
            m = fmaxf(m, r);
        }
    }
    #pragma unroll
    for (int o = 16; o > 0; o >>= 1) m = fmaxf(m, __shfl_xor_sync(0xffffffffu, m, o));

    // pass 2: exp-weighted sum
    float num = 0.f, den = 0.f;
    if (sA >= 0){ float w = __expf(rA - m); num += __ldg(&g_xs2[sA])*w; den += w; }
    if (sB >= 0){ float w = __expf(rB - m); num += __ldg(&g_xs2[sB])*w; den += w; }
    for (int j = 2; j < nIter; j++){
        int i = lane + 32*j;
        if (i < deg){
            float4 er = __ldg(&g_er[start + i]);
            int s = __float_as_int(er.w);
            float ea = __ldg(&g_eea[start + i]);
            float r = lrelu(__ldg(&g_a2s[s]) + ad + ea*ce);
            float w = __expf(r - m);
            num += __ldg(&g_xs2[s])*w; den += w;
        }
    }
    #pragma unroll
    for (int o = 16; o > 0; o >>= 1){
        num += __shfl_xor_sync(0xffffffffu, num, o);
        den += __shfl_xor_sync(0xffffffffu, den, o);
    }
    if (lane == 0){
        float v = num / (den + 1e-16f) + b2[0];
        out[n] = v * x[n*5 + 0];
    }
}

// ---------------- launch ----------------
extern "C" void kernel_launch(void* const* d_in, const int* in_sizes, int n_in,
                              void* d_out, int out_size){
    const float* x        = (const float*)d_in[0];
    const void*  ei       = d_in[1];
    const float* eattr    = (const float*)d_in[2];
    const float* W_comm   = (const float*)d_in[3];
    const float* b_comm   = (const float*)d_in[4];
    const float* W_toll   = (const float*)d_in[5];
    const float* b_toll   = (const float*)d_in[6];
    const float* W1_src   = (const float*)d_in[7];
    const float* W1_dst   = (const float*)d_in[8];
    const float* att1_src = (const float*)d_in[9];
    const float* att1_dst = (const float*)d_in[10];
    const float* W1_edge  = (const float*)d_in[11];
    const float* att1_edge= (const float*)d_in[12];
    const float* b1       = (const float*)d_in[13];
    const float* W2_src   = (const float*)d_in[14];
    const float* W2_dst   = (const float*)d_in[15];
    const float* att2_src = (const float*)d_in[16];
    const float* att2_dst = (const float*)d_in[17];
    const float* W2_edge  = (const float*)d_in[18];
    const float* att2_edge= (const float*)d_in[19];
    const float* b2       = (const float*)d_in[20];
    float* out = (float*)d_out;

    k_front<<<(NN*HID)/256 + 1, 256>>>(x, W_comm, b_comm, W_toll, b_toll,
                                       W1_dst, att1_dst, W1_edge, att1_edge,
                                       (const int*)ei);
    k_edges<<<(EE + 255)/256, 256>>>(ei);
    k_scan<<<1, 1024>>>();
    k_xs<<<NN, 192>>>(W1_src, att1_src);
    k_scatter<<<(EE + 255)/256, 256>>>(eattr);
    k_l1<<<(NN + 7)/8, 256>>>(b1, W2_src, W2_dst, att2_src, att2_dst);
    k_l2<<<(NN + 7)/8, 256>>>(x, W2_edge, att2_edge, b2, out);
}

// round 6
// speedup vs baseline: 2.0557x; 1.3573x over previous
#include <cuda_runtime.h>
#include <math.h>

#define NN 50000
#define EE 800000
#define HID 64
#define NH 3
#define D1 192   // NH*HID
#define TN 16    // nodes per k_xs block

// ---------------- scratch (device globals) ----------------
__device__ float  g_xs1[NN*D1];    // h @ W1_src
__device__ float  g_as1[NN*4];     // per-node a_src (3 used, padded to float4; .w unused)
__device__ float  g_ad1[NN*4];     // per-node a_dst
__device__ int    g_src[EE];
__device__ int    g_dst[EE];
__device__ int    g_deg[NN];
__device__ int    g_rowptr[NN+1];
__device__ int    g_cursor[NN];
__device__ float4 g_er[EE];        // per-edge {r0,r1,r2,src_bits} grouped by dst
__device__ float  g_eea[EE];       // per-edge edge_attr grouped by dst
__device__ float  g_xs2[NN];       // h1 @ W2_src
__device__ float  g_a2s[NN];       // xs2 * att2_src
__device__ float  g_a2d[NN];       // (h1 @ W2_dst) * att2_dst
__device__ float  g_watt[HID*6];   // [k*6+q]: q<3 -> fold(W1_src,att1_src), q>=3 -> fold(W1_dst,att1_dst)
__device__ float  g_ce1[NH];
__device__ int    g_is64;

__device__ __forceinline__ float lrelu(float v){ return v > 0.f ? v : 0.2f*v; }

// ---------------- front: zero deg + folds + dtype detect ----------------
__global__ void k_front(const float* __restrict__ W1_src, const float* __restrict__ att1_src,
                        const float* __restrict__ W1_dst, const float* __restrict__ att1_dst,
                        const float* __restrict__ W1_edge, const float* __restrict__ att1_edge,
                        const int*   __restrict__ ei){
    int tid = threadIdx.x;
    if (blockIdx.x == (NN + 255)/256){
        // folds: g_watt[k*6+q]
        for (int i = tid; i < HID*6; i += 256){
            int k = i / 6, q = i % 6;
            float s = 0.f;
            const float* W   = (q < 3) ? W1_src   : W1_dst;
            const float* att = (q < 3) ? att1_src : att1_dst;
            int h = (q < 3) ? q : q - 3;
            #pragma unroll 8
            for (int c = 0; c < HID; c++)
                s += W[k*D1 + h*HID + c] * att[h*HID + c];
            g_watt[i] = s;
        }
        if (tid < 3){
            float s = 0.f;
            #pragma unroll 8
            for (int c = 0; c < HID; c++)
                s += W1_edge[tid*HID + c] * att1_edge[tid*HID + c];
            g_ce1[tid] = s;
        }
        if (tid == 255){
            int all0 = 1;
            for (int i = 0; i < 64; i++) if (ei[2*i+1] != 0) all0 = 0;
            g_is64 = all0;
        }
        return;
    }
    int idx = blockIdx.x * 256 + tid;
    if (idx < NN) g_deg[idx] = 0;
}

// ---------------- edges: decode + degree histogram ----------------
__global__ void k_edges(const void* eiv){
    int e = blockIdx.x * blockDim.x + threadIdx.x;
    if (e >= EE) return;
    int s, d;
    if (g_is64){
        const long long* p = (const long long*)eiv;
        s = (int)p[e]; d = (int)p[EE + e];
    } else {
        const int* p = (const int*)eiv;
        s = p[e]; d = p[EE + e];
    }
    g_src[e] = s; g_dst[e] = d;
    atomicAdd(&g_deg[d], 1);
}

// ---------------- single-block scan ----------------
__global__ void k_scan(){
    __shared__ int sh[1024];
    int tid = threadIdx.x;
    const int ITEMS = 49;     // 1024*49 >= NN
    int base = tid * ITEMS;
    int sum = 0;
    for (int i = 0; i < ITEMS; i++){ int idx = base + i; if (idx < NN) sum += g_deg[idx]; }
    sh[tid] = sum; __syncthreads();
    for (int off = 1; off < 1024; off <<= 1){
        int t = (tid >= off) ? sh[tid - off] : 0;
        __syncthreads();
        sh[tid] += t;
        __syncthreads();
    }
    int run = sh[tid] - sum;  // exclusive prefix
    for (int i = 0; i < ITEMS; i++){
        int idx = base + i;
        if (idx < NN){ g_rowptr[idx] = run; g_cursor[idx] = run; run += g_deg[idx]; }
    }
    if (tid == 1023) g_rowptr[NN] = sh[1023];
}

// ---------------- fused encoder + xs1 GEMM + a_src/a_dst ----------------
// block: 192 threads, TN=16 nodes; thread tile 4 nodes x 4 cols
__global__ void __launch_bounds__(192) k_xs(const float* __restrict__ x,
                                            const float* __restrict__ W1_src,
                                            const float* __restrict__ Wc, const float* __restrict__ bc,
                                            const float* __restrict__ Wt, const float* __restrict__ bt){
    __shared__ float A[HID][TN];     // A[k][n] : h values, node-contiguous (rows 64B aligned)
    __shared__ float sx[TN*5];
    __shared__ float sW[5*HID];      // [0:128)=Wc, [128:192)=Wt, [192:256)=bc, [256:320)=bt
    int tid = threadIdx.x;
    int nb = blockIdx.x * TN;

    if (tid < 128) sW[tid] = Wc[tid];
    else if (tid < 192) sW[tid] = Wt[tid - 128];
    if (tid < 64) sW[192 + tid] = bc[tid];
    else if (tid < 128) sW[192 + tid] = bt[tid - 64];
    if (tid < TN*5) sx[tid] = x[nb*5 + tid];
    __syncthreads();

    // fill A with encoder output (fused ELU)
    for (int i = tid; i < HID*TN; i += 192){
        int k = i / TN, n = i % TN;
        float mask = sx[n*5+0], f0 = sx[n*5+1], f1 = sx[n*5+2], f2 = sx[n*5+3];
        float comm = f0*sW[k] + f1*sW[64+k] + sW[192+k];
        float toll = f2*sW[128+k] + sW[256+k];
        float v = comm*(1.f - mask) + toll*mask;
        A[k][n] = v > 0.f ? v : expm1f(v);
    }
    __syncthreads();

    // register-tiled GEMM: ty in [0,4) -> nodes 4*ty.., tx in [0,48) -> cols 4*tx..
    int tx = tid % 48, ty = tid / 48;
    const float4* A4 = (const float4*)A;   // A4[k*4 + ty] = 4 nodes' values at k
    float4 c0 = {0,0,0,0}, c1 = {0,0,0,0}, c2 = {0,0,0,0}, c3 = {0,0,0,0};
    #pragma unroll 4
    for (int k = 0; k < HID; k++){
        float4 w = __ldg((const float4*)&W1_src[k*D1 + tx*4]);
        float4 a = A4[k*4 + ty];
        c0.x += a.x*w.x; c0.y += a.x*w.y; c0.z += a.x*w.z; c0.w += a.x*w.w;
        c1.x += a.y*w.x; c1.y += a.y*w.y; c1.z += a.y*w.z; c1.w += a.y*w.w;
        c2.x += a.z*w.x; c2.y += a.z*w.y; c2.z += a.z*w.z; c2.w += a.z*w.w;
        c3.x += a.w*w.x; c3.y += a.w*w.y; c3.z += a.w*w.z; c3.w += a.w*w.w;
    }
    int n0 = nb + ty*4;
    *(float4*)&g_xs1[(n0+0)*D1 + tx*4] = c0;
    *(float4*)&g_xs1[(n0+1)*D1 + tx*4] = c1;
    *(float4*)&g_xs1[(n0+2)*D1 + tx*4] = c2;
    *(float4*)&g_xs1[(n0+3)*D1 + tx*4] = c3;

    // a_src / a_dst: 16 nodes x 6 projections (threads 0..95)
    if (tid < TN*6){
        int n = tid / 6, q = tid % 6;
        float s = 0.f;
        #pragma unroll 8
        for (int k = 0; k < HID; k++)
            s += A[k][n] * g_watt[k*6 + q];
        if (q < 3) g_as1[(nb+n)*4 + q] = s;
        else       g_ad1[(nb+n)*4 + (q-3)] = s;
    }
}

// ---------------- scatter: CSR + fused per-edge attention logits ----------------
__global__ void k_scatter(const float* __restrict__ edge_attr){
    int e = blockIdx.x * blockDim.x + threadIdx.x;
    if (e >= EE) return;
    int s = g_src[e], d = g_dst[e];
    float ea = __ldg(&edge_attr[e]);
    float4 as = *(const float4*)&g_as1[s*4];
    float4 ad = *(const float4*)&g_ad1[d*4];
    float r0 = lrelu(as.x + ad.x + ea*g_ce1[0]);
    float r1 = lrelu(as.y + ad.y + ea*g_ce1[1]);
    float r2 = lrelu(as.z + ad.z + ea*g_ce1[2]);
    int p = atomicAdd(&g_cursor[d], 1);
    g_er[p] = make_float4(r0, r1, r2, __int_as_float(s));
    g_eea[p] = ea;
}

// ---------------- layer-1 warp-per-node aggregation + fused layer-2 proj ----------------
__global__ void __launch_bounds__(256) k_l1(const float* __restrict__ b1,
                                            const float* __restrict__ W2_src,
                                            const float* __restrict__ W2_dst,
                                            const float* __restrict__ att2_src,
                                            const float* __restrict__ att2_dst){
    __shared__ float4 s_w[8][32];
    int wslot = threadIdx.x >> 5, lane = threadIdx.x & 31;
    int n = blockIdx.x * 8 + wslot;
    if (n >= NN) return;                 // warp-uniform
    int start = g_rowptr[n], deg = g_rowptr[n+1] - start;

    // pass A: per-head max (contiguous reads)
    float m0 = -1e30f, m1 = -1e30f, m2 = -1e30f;
    {
        int i = lane;
        for (; i + 32 < deg; i += 64){
            float4 ea = __ldg(&g_er[start + i]);
            float4 eb = __ldg(&g_er[start + i + 32]);
            m0 = fmaxf(m0, fmaxf(ea.x, eb.x));
            m1 = fmaxf(m1, fmaxf(ea.y, eb.y));
            m2 = fmaxf(m2, fmaxf(ea.z, eb.z));
        }
        if (i < deg){
            float4 ea = __ldg(&g_er[start + i]);
            m0 = fmaxf(m0, ea.x); m1 = fmaxf(m1, ea.y); m2 = fmaxf(m2, ea.z);
        }
    }
    #pragma unroll
    for (int o = 16; o > 0; o >>= 1){
        m0 = fmaxf(m0, __shfl_xor_sync(0xffffffffu, m0, o));
        m1 = fmaxf(m1, __shfl_xor_sync(0xffffffffu, m1, o));
        m2 = fmaxf(m2, __shfl_xor_sync(0xffffffffu, m2, o));
    }

    // pass B: exp weights + gather
    float acc0=0.f,acc1=0.f,acc2=0.f,acc3=0.f,acc4=0.f,acc5=0.f;
    float den0=0.f,den1=0.f,den2=0.f;
    for (int base = 0; base < deg; base += 32){
        int cn = min(32, deg - base);
        if (lane < cn){
            float4 er = __ldg(&g_er[start + base + lane]);
            float w0 = __expf(er.x - m0);
            float w1 = __expf(er.y - m1);
            float w2 = __expf(er.z - m2);
            den0 += w0; den1 += w1; den2 += w2;
            s_w[wslot][lane] = make_float4(w0, w1, w2, er.w);
        }
        __syncwarp();
        #pragma unroll 2
        for (int i = 0; i < cn; i++){
            float4 w = s_w[wslot][i];
            const float* row = &g_xs1[__float_as_int(w.w) * D1];
            acc0 += __ldg(&row[lane      ]) * w.x;
            acc1 += __ldg(&row[lane + 32 ]) * w.x;
            acc2 += __ldg(&row[lane + 64 ]) * w.y;
            acc3 += __ldg(&row[lane + 96 ]) * w.y;
            acc4 += __ldg(&row[lane + 128]) * w.z;
            acc5 += __ldg(&row[lane + 160]) * w.z;
        }
        __syncwarp();
    }
    #pragma unroll
    for (int o = 16; o > 0; o >>= 1){
        den0 += __shfl_xor_sync(0xffffffffu, den0, o);
        den1 += __shfl_xor_sync(0xffffffffu, den1, o);
        den2 += __shfl_xor_sync(0xffffffffu, den2, o);
    }
    float id0 = 1.f/(den0 + 1e-16f), id1 = 1.f/(den1 + 1e-16f), id2 = 1.f/(den2 + 1e-16f);

    // h1 channels for this lane: lane+32c; fused layer-2 projections
    float vs = 0.f, vd = 0.f;
    float accs[6] = {acc0*id0, acc1*id0, acc2*id1, acc3*id1, acc4*id2, acc5*id2};
    #pragma unroll
    for (int c = 0; c < 6; c++){
        int ch = lane + 32*c;
        float o = accs[c] + __ldg(&b1[ch]);
        float hv = o > 0.f ? o : expm1f(o);
        vs += hv * __ldg(&W2_src[ch]);
        vd += hv * __ldg(&W2_dst[ch]);
    }
    #pragma unroll
    for (int o = 16; o > 0; o >>= 1){
        vs += __shfl_xor_sync(0xffffffffu, vs, o);
        vd += __shfl_xor_sync(0xffffffffu, vd, o);
    }
    if (lane == 0){
        g_xs2[n] = vs;
        g_a2s[n] = vs * att2_src[0];
        g_a2d[n] = vd * att2_dst[0];
    }
}

// ---------------- layer-2 warp-per-node aggregation + final mask ----------------
__global__ void __launch_bounds__(256) k_l2(const float* __restrict__ x,
                                            const float* __restrict__ W2_edge,
                                            const float* __restrict__ att2_edge,
                                            const float* __restrict__ b2,
                                            float* __restrict__ out){
    int wslot = threadIdx.x >> 5, lane = threadIdx.x & 31;
    int n = blockIdx.x * 8 + wslot;
    if (n >= NN) return;
    int start = g_rowptr[n], deg = g_rowptr[n+1] - start;
    float ce = W2_edge[0] * att2_edge[0];
    float ad = g_a2d[n];

    // pass 1: max, with 2-slot register cache (covers deg <= 64)
    float rA = -1e30f, rB = -1e30f;
    int   sA = -1,     sB = -1;
    float m = -1e30f;
    int nIter = (deg + 31) >> 5;
    for (int j = 0; j < nIter; j++){
        int i = lane + 32*j;
        if (i < deg){
            float4 er = __ldg(&g_er[start + i]);
            int s = __float_as_int(er.w);
            float ea = __ldg(&g_eea[start + i]);
            float r = lrelu(__ldg(&g_a2s[s]) + ad + ea*ce);
            if (j == 0){ rA = r; sA = s; }
            else if (j == 1){ rB = r; sB = s; }
            m = fmaxf(m, r);
        }
    }
    #pragma unroll
    for (int o = 16; o > 0; o >>= 1) m = fmaxf(m, __shfl_xor_sync(0xffffffffu, m, o));

    // pass 2: exp-weighted sum
    float num = 0.f, den = 0.f;
    if (sA >= 0){ float w = __expf(rA - m); num += __ldg(&g_xs2[sA])*w; den += w; }
    if (sB >= 0){ float w = __expf(rB - m); num += __ldg(&g_xs2[sB])*w; den += w; }
    for (int j = 2; j < nIter; j++){
        int i = lane + 32*j;
        if (i < deg){
            float4 er = __ldg(&g_er[start + i]);
            int s = __float_as_int(er.w);
            float ea = __ldg(&g_eea[start + i]);
            float r = lrelu(__ldg(&g_a2s[s]) + ad + ea*ce);
            float w = __expf(r - m);
            num += __ldg(&g_xs2[s])*w; den += w;
        }
    }
    #pragma unroll
    for (int o = 16; o > 0; o >>= 1){
        num += __shfl_xor_sync(0xffffffffu, num, o);
        den += __shfl_xor_sync(0xffffffffu, den, o);
    }
    if (lane == 0){
        float v = num / (den + 1e-16f) + b2[0];
        out[n] = v * x[n*5 + 0];
    }
}

// ---------------- launch ----------------
extern "C" void kernel_launch(void* const* d_in, const int* in_sizes, int n_in,
                              void* d_out, int out_size){
    const float* x        = (const float*)d_in[0];
    const void*  ei       = d_in[1];
    const float* eattr    = (const float*)d_in[2];
    const float* W_comm   = (const float*)d_in[3];
    const float* b_comm   = (const float*)d_in[4];
    const float* W_toll   = (const float*)d_in[5];
    const float* b_toll   = (const float*)d_in[6];
    const float* W1_src   = (const float*)d_in[7];
    const float* W1_dst   = (const float*)d_in[8];
    const float* att1_src = (const float*)d_in[9];
    const float* att1_dst = (const float*)d_in[10];
    const float* W1_edge  = (const float*)d_in[11];
    const float* att1_edge= (const float*)d_in[12];
    const float* b1       = (const float*)d_in[13];
    const float* W2_src   = (const float*)d_in[14];
    const float* W2_dst   = (const float*)d_in[15];
    const float* att2_src = (const float*)d_in[16];
    const float* att2_dst = (const float*)d_in[17];
    const float* W2_edge  = (const float*)d_in[18];
    const float* att2_edge= (const float*)d_in[19];
    const float* b2       = (const float*)d_in[20];
    float* out = (float*)d_out;

    k_front<<<(NN + 255)/256 + 1, 256>>>(W1_src, att1_src, W1_dst, att1_dst,
                                         W1_edge, att1_edge, (const int*)ei);
    k_edges<<<(EE + 255)/256, 256>>>(ei);
    k_scan<<<1, 1024>>>();
    k_xs<<<NN/TN, 192>>>(x, W1_src, W_comm, b_comm, W_toll, b_toll);
    k_scatter<<<(EE + 255)/256, 256>>>(eattr);
    k_l1<<<(NN + 7)/8, 256>>>(b1, W2_src, W2_dst, att2_src, att2_dst);
    k_l2<<<(NN + 7)/8, 256>>>(x, W2_edge, att2_edge, b2, out);
}

// round 9
// speedup vs baseline: 2.1582x; 1.0499x over previous
#include <cuda_runtime.h>
#include <math.h>

#define NN 50000
#define EE 800000
#define HID 64
#define NH 3
#define D1 192   // NH*HID
#define TN 16    // nodes per k_xs block

// ---------------- scratch (device globals) ----------------
__device__ float  g_xs1[NN*D1];    // h @ W1_src
__device__ float  g_as1[NN*4];     // per-node a_src (3 used, padded to float4)
__device__ float  g_ad1[NN*4];     // per-node a_dst
__device__ int    g_src[EE];
__device__ int    g_dst[EE];
__device__ int    g_deg[NN];
__device__ int    g_rowptr[NN+1];
__device__ int    g_cursor[NN];
__device__ float4 g_er[EE];        // per-edge {r0,r1,r2,src_bits} grouped by dst
__device__ float  g_eea[EE];       // per-edge edge_attr*ce2 grouped by dst
__device__ float2 g_a2sx[NN];      // {a2s, xs2}
__device__ float  g_a2d[NN];       // (h1 @ W2_dst) * att2_dst
__device__ float  g_watt[HID*6];   // [k*6+q]: q<3 -> fold(W1_src,att1_src), q>=3 -> fold(W1_dst,att1_dst)
__device__ float  g_ce1[NH];
__device__ float  g_ce2;
__device__ int    g_is64;

__device__ __forceinline__ float lrelu(float v){ return v > 0.f ? v : 0.2f*v; }

// ---------------- front: zero deg + folds + dtype detect ----------------
__global__ void k_front(const float* __restrict__ W1_src, const float* __restrict__ att1_src,
                        const float* __restrict__ W1_dst, const float* __restrict__ att1_dst,
                        const float* __restrict__ W1_edge, const float* __restrict__ att1_edge,
                        const float* __restrict__ W2_edge, const float* __restrict__ att2_edge,
                        const int*   __restrict__ ei){
    int tid = threadIdx.x;
    if (blockIdx.x == (NN + 255)/256){
        for (int i = tid; i < HID*6; i += 256){
            int k = i / 6, q = i % 6;
            float s = 0.f;
            const float* W   = (q < 3) ? W1_src   : W1_dst;
            const float* att = (q < 3) ? att1_src : att1_dst;
            int h = (q < 3) ? q : q - 3;
            #pragma unroll 8
            for (int c = 0; c < HID; c++)
                s += W[k*D1 + h*HID + c] * att[h*HID + c];
            g_watt[i] = s;
        }
        if (tid < 3){
            float s = 0.f;
            #pragma unroll 8
            for (int c = 0; c < HID; c++)
                s += W1_edge[tid*HID + c] * att1_edge[tid*HID + c];
            g_ce1[tid] = s;
        }
        if (tid == 254) g_ce2 = W2_edge[0] * att2_edge[0];
        if (tid == 255){
            int all0 = 1;
            for (int i = 0; i < 64; i++) if (ei[2*i+1] != 0) all0 = 0;
            g_is64 = all0;
        }
        return;
    }
    int idx = blockIdx.x * 256 + tid;
    if (idx < NN) g_deg[idx] = 0;
}

// ---------------- edges: decode + degree histogram ----------------
__global__ void k_edges(const void* eiv){
    int e = blockIdx.x * blockDim.x + threadIdx.x;
    if (e >= EE) return;
    int s, d;
    if (g_is64){
        const long long* p = (const long long*)eiv;
        s = (int)p[e]; d = (int)p[EE + e];
    } else {
        const int* p = (const int*)eiv;
        s = p[e]; d = p[EE + e];
    }
    g_src[e] = s; g_dst[e] = d;
    atomicAdd(&g_deg[d], 1);
}

// ---------------- single-block scan ----------------
__global__ void k_scan(){
    __shared__ int sh[1024];
    int tid = threadIdx.x;
    const int ITEMS = 49;     // 1024*49 >= NN
    int base = tid * ITEMS;
    int sum = 0;
    for (int i = 0; i < ITEMS; i++){ int idx = base + i; if (idx < NN) sum += g_deg[idx]; }
    sh[tid] = sum; __syncthreads();
    for (int off = 1; off < 1024; off <<= 1){
        int t = (tid >= off) ? sh[tid - off] : 0;
        __syncthreads();
        sh[tid] += t;
        __syncthreads();
    }
    int run = sh[tid] - sum;  // exclusive prefix
    for (int i = 0; i < ITEMS; i++){
        int idx = base + i;
        if (idx < NN){ g_rowptr[idx] = run; g_cursor[idx] = run; run += g_deg[idx]; }
    }
    if (tid == 1023) g_rowptr[NN] = sh[1023];
}

// ---------------- fused encoder + xs1 GEMM + a_src/a_dst ----------------
__global__ void __launch_bounds__(192) k_xs(const float* __restrict__ x,
                                            const float* __restrict__ W1_src,
                                            const float* __restrict__ Wc, const float* __restrict__ bc,
                                            const float* __restrict__ Wt, const float* __restrict__ bt){
    __shared__ float A[HID][TN];     // A[k][n] : h values
    __shared__ float sx[TN*5];
    __shared__ float sW[5*HID];
    int tid = threadIdx.x;
    int nb = blockIdx.x * TN;

    if (tid < 128) sW[tid] = Wc[tid];
    else if (tid < 192) sW[tid] = Wt[tid - 128];
    if (tid < 64) sW[192 + tid] = bc[tid];
    else if (tid < 128) sW[192 + tid] = bt[tid - 64];
    if (tid < TN*5) sx[tid] = x[nb*5 + tid];
    __syncthreads();

    for (int i = tid; i < HID*TN; i += 192){
        int k = i / TN, n = i % TN;
        float mask = sx[n*5+0], f0 = sx[n*5+1], f1 = sx[n*5+2], f2 = sx[n*5+3];
        float comm = f0*sW[k] + f1*sW[64+k] + sW[192+k];
        float toll = f2*sW[128+k] + sW[256+k];
        float v = comm*(1.f - mask) + toll*mask;
        A[k][n] = v > 0.f ? v : expm1f(v);
    }
    __syncthreads();

    int tx = tid % 48, ty = tid / 48;
    const float4* A4 = (const float4*)A;
    float4 c0 = {0,0,0,0}, c1 = {0,0,0,0}, c2 = {0,0,0,0}, c3 = {0,0,0,0};
    #pragma unroll 4
    for (int k = 0; k < HID; k++){
        float4 w = __ldg((const float4*)&W1_src[k*D1 + tx*4]);
        float4 a = A4[k*4 + ty];
        c0.x += a.x*w.x; c0.y += a.x*w.y; c0.z += a.x*w.z; c0.w += a.x*w.w;
        c1.x += a.y*w.x; c1.y += a.y*w.y; c1.z += a.y*w.z; c1.w += a.y*w.w;
        c2.x += a.z*w.x; c2.y += a.z*w.y; c2.z += a.z*w.z; c2.w += a.z*w.w;
        c3.x += a.w*w.x; c3.y += a.w*w.y; c3.z += a.w*w.z; c3.w += a.w*w.w;
    }
    int n0 = nb + ty*4;
    *(float4*)&g_xs1[(n0+0)*D1 + tx*4] = c0;
    *(float4*)&g_xs1[(n0+1)*D1 + tx*4] = c1;
    *(float4*)&g_xs1[(n0+2)*D1 + tx*4] = c2;
    *(float4*)&g_xs1[(n0+3)*D1 + tx*4] = c3;

    if (tid < TN*6){
        int n = tid / 6, q = tid % 6;
        float s = 0.f;
        #pragma unroll 8
        for (int k = 0; k < HID; k++)
            s += A[k][n] * g_watt[k*6 + q];
        if (q < 3) g_as1[(nb+n)*4 + q] = s;
        else       g_ad1[(nb+n)*4 + (q-3)] = s;
    }
}

// ---------------- scatter: CSR + fused per-edge attention logits ----------------
__global__ void k_scatter(const float* __restrict__ edge_attr){
    int e = blockIdx.x * blockDim.x + threadIdx.x;
    if (e >= EE) return;
    int s = g_src[e], d = g_dst[e];
    float ea = __ldg(&edge_attr[e]);
    float4 as = *(const float4*)&g_as1[s*4];
    float4 ad = *(const float4*)&g_ad1[d*4];
    float r0 = lrelu(as.x + ad.x + ea*g_ce1[0]);
    float r1 = lrelu(as.y + ad.y + ea*g_ce1[1]);
    float r2 = lrelu(as.z + ad.z + ea*g_ce1[2]);
    int p = atomicAdd(&g_cursor[d], 1);
    g_er[p] = make_float4(r0, r1, r2, __int_as_float(s));
    g_eea[p] = ea * g_ce2;
}

// ---------------- layer-1 warp-per-node aggregation (single pass, no max) ----------------
__global__ void __launch_bounds__(256) k_l1(const float* __restrict__ b1,
                                            const float* __restrict__ W2_src,
                                            const float* __restrict__ W2_dst,
                                            const float* __restrict__ att2_src,
                                            const float* __restrict__ att2_dst){
    __shared__ float4 s_w[8][32];
    int wslot = threadIdx.x >> 5, lane = threadIdx.x & 31;
    int n = blockIdx.x * 8 + wslot;
    if (n >= NN) return;                 // warp-uniform
    int start = g_rowptr[n], deg = g_rowptr[n+1] - start;

    // single pass: exp weights + row gathers (normalization deferred; no max needed)
    float2 acc0 = {0,0}, acc1 = {0,0}, acc2 = {0,0};
    float den0=0.f, den1=0.f, den2=0.f;
    for (int base = 0; base < deg; base += 32){
        int cn = min(32, deg - base);
        if (lane < cn){
            float4 er = __ldg(&g_er[start + base + lane]);
            float w0 = __expf(er.x);
            float w1 = __expf(er.y);
            float w2 = __expf(er.z);
            den0 += w0; den1 += w1; den2 += w2;
            s_w[wslot][lane] = make_float4(w0, w1, w2, er.w);
        }
        __syncwarp();
        #pragma unroll 2
        for (int i = 0; i < cn; i++){
            float4 w = s_w[wslot][i];
            const float2* row2 = (const float2*)&g_xs1[__float_as_int(w.w) * D1];
            float2 v0 = __ldg(&row2[lane      ]);   // head 0: ch 2*lane, 2*lane+1
            float2 v1 = __ldg(&row2[lane + 32 ]);   // head 1: ch 64+2*lane..
            float2 v2 = __ldg(&row2[lane + 64 ]);   // head 2: ch 128+2*lane..
            acc0.x += v0.x*w.x; acc0.y += v0.y*w.x;
            acc1.x += v1.x*w.y; acc1.y += v1.y*w.y;
            acc2.x += v2.x*w.z; acc2.y += v2.y*w.z;
        }
        __syncwarp();
    }
    #pragma unroll
    for (int o = 16; o > 0; o >>= 1){
        den0 += __shfl_xor_sync(0xffffffffu, den0, o);
        den1 += __shfl_xor_sync(0xffffffffu, den1, o);
        den2 += __shfl_xor_sync(0xffffffffu, den2, o);
    }
    float id0 = 1.f/(den0 + 1e-16f), id1 = 1.f/(den1 + 1e-16f), id2 = 1.f/(den2 + 1e-16f);

    // epilogue: bias+ELU then fused layer-2 projections (channels 64h+2*lane+{0,1})
    float vs = 0.f, vd = 0.f;
    float2 accs[3] = { make_float2(acc0.x*id0, acc0.y*id0),
                       make_float2(acc1.x*id1, acc1.y*id1),
                       make_float2(acc2.x*id2, acc2.y*id2) };
    #pragma unroll
    for (int h = 0; h < 3; h++){
        int ci = h*32 + lane;
        float2 bb = __ldg(&((const float2*)b1)[ci]);
        float2 ws = __ldg(&((const float2*)W2_src)[ci]);
        float2 wdv = __ldg(&((const float2*)W2_dst)[ci]);
        float o0 = accs[h].x + bb.x, o1 = accs[h].y + bb.y;
        float h0 = o0 > 0.f ? o0 : expm1f(o0);
        float h1 = o1 > 0.f ? o1 : expm1f(o1);
        vs += h0*ws.x + h1*ws.y;
        vd += h0*wdv.x + h1*wdv.y;
    }
    #pragma unroll
    for (int o = 16; o > 0; o >>= 1){
        vs += __shfl_xor_sync(0xffffffffu, vs, o);
        vd += __shfl_xor_sync(0xffffffffu, vd, o);
    }
    if (lane == 0){
        g_a2sx[n] = make_float2(vs * att2_src[0], vs);
        g_a2d[n]  = vd * att2_dst[0];
    }
}

// ---------------- layer-2 single-pass warp-per-node aggregation + final mask ----------------
__global__ void __launch_bounds__(256) k_l2(const float* __restrict__ x,
                                            const float* __restrict__ b2,
                                            float* __restrict__ out){
    int wslot = threadIdx.x >> 5, lane = threadIdx.x & 31;
    int n = blockIdx.x * 8 + wslot;
    if (n >= NN) return;
    int start = g_rowptr[n], deg = g_rowptr[n+1] - start;
    float ad = g_a2d[n];

    float num = 0.f, den = 0.f;
    for (int i = lane; i < deg; i += 32){
        float4 er = __ldg(&g_er[start + i]);
        int s = __float_as_int(er.w);
        float eace = __ldg(&g_eea[start + i]);
        float2 a2 = __ldg(&g_a2sx[s]);          // {a2s, xs2}
        float r = lrelu(a2.x + ad + eace);
        float w = __expf(r);
        num += a2.y * w;
        den += w;
    }
    #pragma unroll
    for (int o = 16; o > 0; o >>= 1){
        num += __shfl_xor_sync(0xffffffffu, num, o);
        den += __shfl_xor_sync(0xffffffffu, den, o);
    }
    if (lane == 0){
        float v = num / (den + 1e-16f) + b2[0];
        out[n] = v * x[n*5 + 0];
    }
}

// ---------------- launch ----------------
extern "C" void kernel_launch(void* const* d_in, const int* in_sizes, int n_in,
                              void* d_out, int out_size){
    const float* x        = (const float*)d_in[0];
    const void*  ei       = d_in[1];
    const float* eattr    = (const float*)d_in[2];
    const float* W_comm   = (const float*)d_in[3];
    const float* b_comm   = (const float*)d_in[4];
    const float* W_toll   = (const float*)d_in[5];
    const float* b_toll   = (const float*)d_in[6];
    const float* W1_src   = (const float*)d_in[7];
    const float* W1_dst   = (const float*)d_in[8];
    const float* att1_src = (const float*)d_in[9];
    const float* att1_dst = (const float*)d_in[10];
    const float* W1_edge  = (const float*)d_in[11];
    const float* att1_edge= (const float*)d_in[12];
    const float* b1       = (const float*)d_in[13];
    const float* W2_src   = (const float*)d_in[14];
    const float* W2_dst   = (const float*)d_in[15];
    const float* att2_src = (const float*)d_in[16];
    const float* att2_dst = (const float*)d_in[17];
    const float* W2_edge  = (const float*)d_in[18];
    const float* att2_edge= (const float*)d_in[19];
    const float* b2       = (const float*)d_in[20];
    float* out = (float*)d_out;

    k_front<<<(NN + 255)/256 + 1, 256>>>(W1_src, att1_src, W1_dst, att1_dst,
                                         W1_edge, att1_edge, W2_edge, att2_edge,
                                         (const int*)ei);
    k_edges<<<(EE + 255)/256, 256>>>(ei);
    k_scan<<<1, 1024>>>();
    k_xs<<<NN/TN, 192>>>(x, W1_src, W_comm, b_comm, W_toll, b_toll);
    k_scatter<<<(EE + 255)/256, 256>>>(eattr);
    k_l1<<<(NN + 7)/8, 256>>>(b1, W2_src, W2_dst, att2_src, att2_dst);
    k_l2<<<(NN + 7)/8, 256>>>(x, b2, out);
}

// round 11
// speedup vs baseline: 2.2272x; 1.0320x over previous
#include <cuda_runtime.h>
#include <cuda_fp16.h>
#include <math.h>

#define NN 50000
#define EE 800000
#define HID 64
#define NH 3
#define D1 192   // NH*HID
#define TN 16    // nodes per k_xs block

// ---------------- scratch (device globals) ----------------
__device__ __half2 g_xs1h[NN*(D1/2)];  // h @ W1_src, fp16 (96 half2 per node)
__device__ float  g_as1[NN*4];     // per-node a_src (3 used, padded to float4)
__device__ float  g_ad1[NN*4];     // per-node a_dst
__device__ int    g_src[EE];
__device__ int    g_dst[EE];
__device__ int    g_deg[NN];
__device__ int    g_rowptr[NN+1];
__device__ int    g_cursor[NN];
__device__ float4 g_er[EE];        // per-edge {w0,w1,w2,src_bits} grouped by dst (w=exp(logit))
__device__ int    g_esrc[EE];      // per-edge src grouped by dst (for k_l2)
__device__ float  g_eea[EE];       // per-edge edge_attr*ce2 grouped by dst
__device__ float2 g_a2sx[NN];      // {a2s, xs2}
__device__ float  g_a2d[NN];       // (h1 @ W2_dst) * att2_dst
__device__ float  g_watt[HID*6];   // [k*6+q]: q<3 -> fold(W1_src,att1_src), q>=3 -> fold(W1_dst,att1_dst)
__device__ float  g_ce1[NH];
__device__ float  g_ce2;
__device__ int    g_is64;

__device__ __forceinline__ float lrelu(float v){ return v > 0.f ? v : 0.2f*v; }

// bit-cast two floats -> packed __half2 -> uint
__device__ __forceinline__ unsigned int f2_to_h2u(float a, float b){
    __half2 h = __floats2half2_rn(a, b);
    union { __half2 h; unsigned int u; } cvt;
    cvt.h = h;
    return cvt.u;
}

// ---------------- front: zero deg + folds + dtype detect ----------------
__global__ void k_front(const float* __restrict__ W1_src, const float* __restrict__ att1_src,
                        const float* __restrict__ W1_dst, const float* __restrict__ att1_dst,
                        const float* __restrict__ W1_edge, const float* __restrict__ att1_edge,
                        const float* __restrict__ W2_edge, const float* __restrict__ att2_edge,
                        const int*   __restrict__ ei){
    int tid = threadIdx.x;
    if (blockIdx.x == (NN + 255)/256){
        for (int i = tid; i < HID*6; i += 256){
            int k = i / 6, q = i % 6;
            float s = 0.f;
            const float* W   = (q < 3) ? W1_src   : W1_dst;
            const float* att = (q < 3) ? att1_src : att1_dst;
            int h = (q < 3) ? q : q - 3;
            #pragma unroll 8
            for (int c = 0; c < HID; c++)
                s += W[k*D1 + h*HID + c] * att[h*HID + c];
            g_watt[i] = s;
        }
        if (tid < 3){
            float s = 0.f;
            #pragma unroll 8
            for (int c = 0; c < HID; c++)
                s += W1_edge[tid*HID + c] * att1_edge[tid*HID + c];
            g_ce1[tid] = s;
        }
        if (tid == 254) g_ce2 = W2_edge[0] * att2_edge[0];
        if (tid == 255){
            int all0 = 1;
            for (int i = 0; i < 64; i++) if (ei[2*i+1] != 0) all0 = 0;
            g_is64 = all0;
        }
        return;
    }
    int idx = blockIdx.x * 256 + tid;
    if (idx < NN) g_deg[idx] = 0;
}

// ---------------- edges: decode + degree histogram ----------------
__global__ void k_edges(const void* eiv){
    int e = blockIdx.x * blockDim.x + threadIdx.x;
    if (e >= EE) return;
    int s, d;
    if (g_is64){
        const long long* p = (const long long*)eiv;
        s = (int)p[e]; d = (int)p[EE + e];
    } else {
        const int* p = (const int*)eiv;
        s = p[e]; d = p[EE + e];
    }
    g_src[e] = s; g_dst[e] = d;
    atomicAdd(&g_deg[d], 1);
}

// ---------------- single-block scan ----------------
__global__ void k_scan(){
    __shared__ int sh[1024];
    int tid = threadIdx.x;
    const int ITEMS = 49;     // 1024*49 >= NN
    int base = tid * ITEMS;
    int sum = 0;
    for (int i = 0; i < ITEMS; i++){ int idx = base + i; if (idx < NN) sum += g_deg[idx]; }
    sh[tid] = sum; __syncthreads();
    for (int off = 1; off < 1024; off <<= 1){
        int t = (tid >= off) ? sh[tid - off] : 0;
        __syncthreads();
        sh[tid] += t;
        __syncthreads();
    }
    int run = sh[tid] - sum;  // exclusive prefix
    for (int i = 0; i < ITEMS; i++){
        int idx = base + i;
        if (idx < NN){ g_rowptr[idx] = run; g_cursor[idx] = run; run += g_deg[idx]; }
    }
    if (tid == 1023) g_rowptr[NN] = sh[1023];
}

// ---------------- fused encoder + xs1 GEMM (fp16 out) + a_src/a_dst ----------------
__global__ void __launch_bounds__(192) k_xs(const float* __restrict__ x,
                                            const float* __restrict__ W1_src,
                                            const float* __restrict__ Wc, const float* __restrict__ bc,
                                            const float* __restrict__ Wt, const float* __restrict__ bt){
    __shared__ float A[HID][TN];     // A[k][n] : h values
    __shared__ float sx[TN*5];
    __shared__ float sW[5*HID];
    int tid = threadIdx.x;
    int nb = blockIdx.x * TN;

    if (tid < 128) sW[tid] = Wc[tid];
    else if (tid < 192) sW[tid] = Wt[tid - 128];
    if (tid < 64) sW[192 + tid] = bc[tid];
    else if (tid < 128) sW[192 + tid] = bt[tid - 64];
    if (tid < TN*5) sx[tid] = x[nb*5 + tid];
    __syncthreads();

    for (int i = tid; i < HID*TN; i += 192){
        int k = i / TN, n = i % TN;
        float mask = sx[n*5+0], f0 = sx[n*5+1], f1 = sx[n*5+2], f2 = sx[n*5+3];
        float comm = f0*sW[k] + f1*sW[64+k] + sW[192+k];
        float toll = f2*sW[128+k] + sW[256+k];
        float v = comm*(1.f - mask) + toll*mask;
        A[k][n] = v > 0.f ? v : expm1f(v);
    }
    __syncthreads();

    int tx = tid % 48, ty = tid / 48;
    const float4* A4 = (const float4*)A;
    float4 c0 = {0,0,0,0}, c1 = {0,0,0,0}, c2 = {0,0,0,0}, c3 = {0,0,0,0};
    #pragma unroll 4
    for (int k = 0; k < HID; k++){
        float4 w = __ldg((const float4*)&W1_src[k*D1 + tx*4]);
        float4 a = A4[k*4 + ty];
        c0.x += a.x*w.x; c0.y += a.x*w.y; c0.z += a.x*w.z; c0.w += a.x*w.w;
        c1.x += a.y*w.x; c1.y += a.y*w.y; c1.z += a.y*w.z; c1.w += a.y*w.w;
        c2.x += a.z*w.x; c2.y += a.z*w.y; c2.z += a.z*w.z; c2.w += a.z*w.w;
        c3.x += a.w*w.x; c3.y += a.w*w.y; c3.z += a.w*w.z; c3.w += a.w*w.w;
    }
    int n0 = nb + ty*4;
    *(uint2*)&g_xs1h[(n0+0)*(D1/2) + tx*2] = make_uint2(f2_to_h2u(c0.x,c0.y), f2_to_h2u(c0.z,c0.w));
    *(uint2*)&g_xs1h[(n0+1)*(D1/2) + tx*2] = make_uint2(f2_to_h2u(c1.x,c1.y), f2_to_h2u(c1.z,c1.w));
    *(uint2*)&g_xs1h[(n0+2)*(D1/2) + tx*2] = make_uint2(f2_to_h2u(c2.x,c2.y), f2_to_h2u(c2.z,c2.w));
    *(uint2*)&g_xs1h[(n0+3)*(D1/2) + tx*2] = make_uint2(f2_to_h2u(c3.x,c3.y), f2_to_h2u(c3.z,c3.w));

    if (tid < TN*6){
        int n = tid / 6, q = tid % 6;
        float s = 0.f;
        #pragma unroll 8
        for (int k = 0; k < HID; k++)
            s += A[k][n] * g_watt[k*6 + q];
        if (q < 3) g_as1[(nb+n)*4 + q] = s;
        else       g_ad1[(nb+n)*4 + (q-3)] = s;
    }
}

// ---------------- scatter: CSR + fused per-edge exp(logit) ----------------
__global__ void k_scatter(const float* __restrict__ edge_attr){
    int e = blockIdx.x * blockDim.x + threadIdx.x;
    if (e >= EE) return;
    int s = g_src[e], d = g_dst[e];
    float ea = __ldg(&edge_attr[e]);
    float4 as = *(const float4*)&g_as1[s*4];
    float4 ad = *(const float4*)&g_ad1[d*4];
    float w0 = __expf(lrelu(as.x + ad.x + ea*g_ce1[0]));
    float w1 = __expf(lrelu(as.y + ad.y + ea*g_ce1[1]));
    float w2 = __expf(lrelu(as.z + ad.z + ea*g_ce1[2]));
    int p = atomicAdd(&g_cursor[d], 1);
    g_er[p] = make_float4(w0, w1, w2, __int_as_float(s));
    g_esrc[p] = s;
    g_eea[p] = ea * g_ce2;
}

// ---------------- layer-1 warp-per-node aggregation (single pass) ----------------
__global__ void __launch_bounds__(256) k_l1(const float* __restrict__ b1,
                                            const float* __restrict__ W2_src,
                                            const float* __restrict__ W2_dst,
                                            const float* __restrict__ att2_src,
                                            const float* __restrict__ att2_dst){
    __shared__ float4 s_w[8][32];
    int wslot = threadIdx.x >> 5, lane = threadIdx.x & 31;
    int n = blockIdx.x * 8 + wslot;
    if (n >= NN) return;                 // warp-uniform
    int start = g_rowptr[n], deg = g_rowptr[n+1] - start;

    float2 acc0 = {0,0}, acc1 = {0,0}, acc2 = {0,0};
    float den0=0.f, den1=0.f, den2=0.f;
    for (int base = 0; base < deg; base += 32){
        int cn = min(32, deg - base);
        if (lane < cn){
            float4 er = __ldg(&g_er[start + base + lane]);   // weights precomputed
            den0 += er.x; den1 += er.y; den2 += er.z;
            s_w[wslot][lane] = er;
        }
        __syncwarp();
        #pragma unroll 2
        for (int i = 0; i < cn; i++){
            float4 w = s_w[wslot][i];
            const __half2* row = &g_xs1h[__float_as_int(w.w) * (D1/2)];
            float2 v0 = __half22float2(__ldg(&row[lane      ]));  // head 0: ch 2*lane..
            float2 v1 = __half22float2(__ldg(&row[lane + 32 ]));  // head 1
            float2 v2 = __half22float2(__ldg(&row[lane + 64 ]));  // head 2
            acc0.x += v0.x*w.x; acc0.y += v0.y*w.x;
            acc1.x += v1.x*w.y; acc1.y += v1.y*w.y;
            acc2.x += v2.x*w.z; acc2.y += v2.y*w.z;
        }
        __syncwarp();
    }
    #pragma unroll
    for (int o = 16; o > 0; o >>= 1){
        den0 += __shfl_xor_sync(0xffffffffu, den0, o);
        den1 += __shfl_xor_sync(0xffffffffu, den1, o);
        den2 += __shfl_xor_sync(0xffffffffu, den2, o);
    }
    float id0 = 1.f/(den0 + 1e-16f), id1 = 1.f/(den1 + 1e-16f), id2 = 1.f/(den2 + 1e-16f);

    // epilogue: bias+ELU then fused layer-2 projections (channels 64h+2*lane+{0,1})
    float vs = 0.f, vd = 0.f;
    float2 accs[3] = { make_float2(acc0.x*id0, acc0.y*id0),
                       make_float2(acc1.x*id1, acc1.y*id1),
                       make_float2(acc2.x*id2, acc2.y*id2) };
    #pragma unroll
    for (int h = 0; h < 3; h++){
        int ci = h*32 + lane;
        float2 bb = __ldg(&((const float2*)b1)[ci]);
        float2 ws = __ldg(&((const float2*)W2_src)[ci]);
        float2 wdv = __ldg(&((const float2*)W2_dst)[ci]);
        float o0 = accs[h].x + bb.x, o1 = accs[h].y + bb.y;
        float h0 = o0 > 0.f ? o0 : expm1f(o0);
        float h1 = o1 > 0.f ? o1 : expm1f(o1);
        vs += h0*ws.x + h1*ws.y;
        vd += h0*wdv.x + h1*wdv.y;
    }
    #pragma unroll
    for (int o = 16; o > 0; o >>= 1){
        vs += __shfl_xor_sync(0xffffffffu, vs, o);
        vd += __shfl_xor_sync(0xffffffffu, vd, o);
    }
    if (lane == 0){
        g_a2sx[n] = make_float2(vs * att2_src[0], vs);
        g_a2d[n]  = vd * att2_dst[0];
    }
}

// ---------------- layer-2 single-pass warp-per-node aggregation + final mask ----------------
__global__ void __launch_bounds__(256) k_l2(const float* __restrict__ x,
                                            const float* __restrict__ b2,
                                            float* __restrict__ out){
    int wslot = threadIdx.x >> 5, lane = threadIdx.x & 31;
    int n = blockIdx.x * 8 + wslot;
    if (n >= NN) return;
    int start = g_rowptr[n], deg = g_rowptr[n+1] - start;
    float ad = g_a2d[n];

    float num = 0.f, den = 0.f;
    for (int i = lane; i < deg; i += 32){
        int s = __ldg(&g_esrc[start + i]);
        float eace = __ldg(&g_eea[start + i]);
        float2 a2 = __ldg(&g_a2sx[s]);          // {a2s, xs2}
        float r = lrelu(a2.x + ad + eace);
        float w = __expf(r);
        num += a2.y * w;
        den += w;
    }
    #pragma unroll
    for (int o = 16; o > 0; o >>= 1){
        num += __shfl_xor_sync(0xffffffffu, num, o);
        den += __shfl_xor_sync(0xffffffffu, den, o);
    }
    if (lane == 0){
        float v = num / (den + 1e-16f) + b2[0];
        out[n] = v * x[n*5 + 0];
    }
}

// ---------------- launch ----------------
extern "C" void kernel_launch(void* const* d_in, const int* in_sizes, int n_in,
                              void* d_out, int out_size){
    const float* x        = (const float*)d_in[0];
    const void*  ei       = d_in[1];
    const float* eattr    = (const float*)d_in[2];
    const float* W_comm   = (const float*)d_in[3];
    const float* b_comm   = (const float*)d_in[4];
    const float* W_toll   = (const float*)d_in[5];
    const float* b_toll   = (const float*)d_in[6];
    const float* W1_src   = (const float*)d_in[7];
    const float* W1_dst   = (const float*)d_in[8];
    const float* att1_src = (const float*)d_in[9];
    const float* att1_dst = (const float*)d_in[10];
    const float* W1_edge  = (const float*)d_in[11];
    const float* att1_edge= (const float*)d_in[12];
    const float* b1       = (const float*)d_in[13];
    const float* W2_src   = (const float*)d_in[14];
    const float* W2_dst   = (const float*)d_in[15];
    const float* att2_src = (const float*)d_in[16];
    const float* att2_dst = (const float*)d_in[17];
    const float* W2_edge  = (const float*)d_in[18];
    const float* att2_edge= (const float*)d_in[19];
    const float* b2       = (const float*)d_in[20];
    float* out = (float*)d_out;

    k_front<<<(NN + 255)/256 + 1, 256>>>(W1_src, att1_src, W1_dst, att1_dst,
                                         W1_edge, att1_edge, W2_edge, att2_edge,
                                         (const int*)ei);
    k_edges<<<(EE + 255)/256, 256>>>(ei);
    k_scan<<<1, 1024>>>();
    k_xs<<<NN/TN, 192>>>(x, W1_src, W_comm, b_comm, W_toll, b_toll);
    k_scatter<<<(EE + 255)/256, 256>>>(eattr);
    k_l1<<<(NN + 7)/8, 256>>>(b1, W2_src, W2_dst, att2_src, att2_dst);
    k_l2<<<(NN + 7)/8, 256>>>(x, b2, out);
}